// round 16
// baseline (speedup 1.0000x reference)
#include <cuda_runtime.h>
#include <cuda_fp16.h>
#include <cstdint>

// Problem constants
#define N_SRC1  292864
#define N_DST1  11264
#define N_E1    281600
#define N_DST2  1024
#define N_E2    10240
#define IN_DIM  256
#define H_DIM   256
#define C_DIM   47

// Scratch (device globals — no allocation allowed)
__device__ __half g_A[N_DST1 * 512];      // [x_dst | hneigh1] fp16
__device__ __half g_WT[256 * 512];        // [Wself1;Wneigh1]^T fp16
__device__ float  g_h[N_DST1 * H_DIM];    // relu(layer-1 out) fp32
__device__ __half g_A2[N_DST2 * 512];     // [h_dst | hneigh2] fp16
__device__ __half g_WT2[64 * 512];        // [Wself2;Wneigh2]^T fp16, cols 47-63 zero

// ---------------------------------------------------------------------------
// fp16 helpers
// ---------------------------------------------------------------------------
__device__ __forceinline__ uint32_t pack_h2(float f0, float f1) {
    const __half h0 = __float2half_rn(f0);
    const __half h1 = __float2half_rn(f1);
    return (uint32_t)__half_as_ushort(h0) | ((uint32_t)__half_as_ushort(h1) << 16);
}
__device__ __forceinline__ void store_h4(__half* p, float4 v) {
    uint2 u;
    u.x = pack_h2(v.x, v.y);
    u.y = pack_h2(v.z, v.w);
    *reinterpret_cast<uint2*>(p) = u;
}

// ---------------------------------------------------------------------------
// cp.async helpers
// ---------------------------------------------------------------------------
__device__ __forceinline__ void cp_async16(uint32_t saddr, const void* g) {
    asm volatile("cp.async.ca.shared.global [%0], [%1], 16;\n"
                 :: "r"(saddr), "l"(g) : "memory");
}
__device__ __forceinline__ void cp_commit() {
    asm volatile("cp.async.commit_group;\n" ::: "memory");
}

// ---------------------------------------------------------------------------
// Layer-1 mean aggregation via cp.async pipelined gather + fused x convert.
// 128 thr/dst: 2 rows per group (64 thr x 16B each), 3-group smem ring.
// Each thread accumulates exactly the bytes it fetched (no block sync in loop).
// A[d][0:256) = fp16(x[d]); A[d][256:512) = fp16(mean of gathered rows).
// ---------------------------------------------------------------------------
#define AGG_G 3   // groups in flight

__global__ __launch_bounds__(128, 16) void agg1_kernel(const float* __restrict__ feat,
                                                       const int* __restrict__ src_idx,
                                                       const int* __restrict__ dst_idx,
                                                       __half* __restrict__ A)
{
    const int d = blockIdx.x;

    int lo = 0, hi = N_E1;
    while (lo < hi) { int mid = (lo + hi) >> 1; if (__ldg(&dst_idx[mid]) < d) lo = mid + 1; else hi = mid; }
    const int start = lo;
    hi = N_E1;
    while (lo < hi) { int mid = (lo + hi) >> 1; if (__ldg(&dst_idx[mid]) <= d) lo = mid + 1; else hi = mid; }
    const int end = lo;
    const int deg = end - start;
    const int ngroups = (deg + 1) >> 1;

    const int t  = threadIdx.x;
    const int p  = t >> 6;              // row parity within a group (0/1)
    const int tt = t & 63;              // 16B slice of the 256-float row

    __shared__ __align__(16) float buf[AGG_G * 2][256];   // 6 KB ring
    __shared__ float a_nb[2][256];

    uint32_t sbase;
    asm("{ .reg .u64 u; cvta.to.shared.u64 u, %1; cvt.u32.u64 %0, u; }"
        : "=r"(sbase) : "l"(buf));
    // this thread's slot address within ring slot s: buf[s*2+p][tt*4]
    const uint32_t myoff = (uint32_t)((p * 256 + tt * 4) * 4);
    const uint32_t slot_bytes = 2 * 256 * 4;

    float4 acc = make_float4(0.f, 0.f, 0.f, 0.f);

    // prologue: issue groups 0..AGG_G-1 (commit even if empty)
#pragma unroll
    for (int g = 0; g < AGG_G; ++g) {
        const int r = 2 * g + p;
        if (g < ngroups && r < deg) {
            const int s = __ldg(&src_idx[start + r]);
            cp_async16(sbase + g * slot_bytes + myoff, &feat[(size_t)s * 256 + tt * 4]);
        }
        cp_commit();
    }

    int slot = 0;
    for (int g = 0; g < ngroups; ++g) {
        asm volatile("cp.async.wait_group %0;" :: "n"(AGG_G - 1) : "memory");

        const int r = 2 * g + p;
        if (r < deg) {
            const float4 v = *reinterpret_cast<const float4*>(&buf[slot * 2 + p][tt * 4]);
            acc.x += v.x; acc.y += v.y; acc.z += v.z; acc.w += v.w;
        }

        // refill this slot with group g+AGG_G
        const int gn = g + AGG_G;
        if (gn < ngroups) {
            const int rn = 2 * gn + p;
            if (rn < deg) {
                const int s = __ldg(&src_idx[start + rn]);
                cp_async16(sbase + slot * slot_bytes + myoff, &feat[(size_t)s * 256 + tt * 4]);
            }
        }
        cp_commit();

        slot = (slot + 1 == AGG_G) ? 0 : slot + 1;
    }

    *reinterpret_cast<float4*>(&a_nb[p][tt * 4]) = acc;

    // fused xcvt: parity-1 threads convert the self row
    if (p == 1) {
        const float4 v = *reinterpret_cast<const float4*>(&feat[(size_t)d * 256 + tt * 4]);
        store_h4(&A[(size_t)d * 512 + tt * 4], v);
    }
    __syncthreads();

    if (p == 0) {
        const float inv = (deg > 0) ? 1.0f / (float)deg : 0.0f;
        float4 u = *reinterpret_cast<float4*>(&a_nb[0][tt * 4]);
        const float4 w = *reinterpret_cast<float4*>(&a_nb[1][tt * 4]);
        u.x = (u.x + w.x) * inv; u.y = (u.y + w.y) * inv;
        u.z = (u.z + w.z) * inv; u.w = (u.w + w.w) * inv;
        store_h4(&A[(size_t)d * 512 + 256 + tt * 4], u);
    }
}

// ---------------------------------------------------------------------------
// Layer-2 aggregation + self copy: 1024 blocks x 256 thr, 4 edge streams.
// ---------------------------------------------------------------------------
__global__ __launch_bounds__(256, 8) void agg2_kernel(const float* __restrict__ h,
                                                      const int* __restrict__ src_idx,
                                                      const int* __restrict__ dst_idx,
                                                      __half* __restrict__ A2)
{
    const int d = blockIdx.x;

    int lo = 0, hi = N_E2;
    while (lo < hi) { int mid = (lo + hi) >> 1; if (__ldg(&dst_idx[mid]) < d) lo = mid + 1; else hi = mid; }
    const int start = lo;
    hi = N_E2;
    while (lo < hi) { int mid = (lo + hi) >> 1; if (__ldg(&dst_idx[mid]) <= d) lo = mid + 1; else hi = mid; }
    const int end = lo;

    const int t  = threadIdx.x;
    const int qs = t >> 6;              // 0..3 edge stream
    const int tt = t & 63;              // float4 slice

    __shared__ float a_nb[4][256];

    float4 acc0 = make_float4(0.f, 0.f, 0.f, 0.f);
    float4 acc1 = make_float4(0.f, 0.f, 0.f, 0.f);

    int e = start + qs;
    for (; e + 4 < end; e += 8) {
        const int s0 = __ldg(&src_idx[e]);
        const int s1 = __ldg(&src_idx[e + 4]);
        const float4 v0 = *reinterpret_cast<const float4*>(&h[(size_t)s0 * 256 + tt * 4]);
        const float4 v1 = *reinterpret_cast<const float4*>(&h[(size_t)s1 * 256 + tt * 4]);
        acc0.x += v0.x; acc0.y += v0.y; acc0.z += v0.z; acc0.w += v0.w;
        acc1.x += v1.x; acc1.y += v1.y; acc1.z += v1.z; acc1.w += v1.w;
    }
    for (; e < end; e += 4) {
        const int s = __ldg(&src_idx[e]);
        const float4 v = *reinterpret_cast<const float4*>(&h[(size_t)s * 256 + tt * 4]);
        acc0.x += v.x; acc0.y += v.y; acc0.z += v.z; acc0.w += v.w;
    }
    acc0.x += acc1.x; acc0.y += acc1.y; acc0.z += acc1.z; acc0.w += acc1.w;
    *reinterpret_cast<float4*>(&a_nb[qs][tt * 4]) = acc0;

    if (qs == 1) {
        const float4 v = *reinterpret_cast<const float4*>(&h[(size_t)d * 256 + tt * 4]);
        store_h4(&A2[(size_t)d * 512 + tt * 4], v);
    }
    __syncthreads();

    if (qs == 0) {
        const int deg = end - start;
        const float inv = (deg > 0) ? 1.0f / (float)deg : 0.0f;
        float4 u = *reinterpret_cast<float4*>(&a_nb[0][tt * 4]);
        const float4 w1 = *reinterpret_cast<float4*>(&a_nb[1][tt * 4]);
        const float4 w2 = *reinterpret_cast<float4*>(&a_nb[2][tt * 4]);
        const float4 w3 = *reinterpret_cast<float4*>(&a_nb[3][tt * 4]);
        u.x = (u.x + w1.x + w2.x + w3.x) * inv;
        u.y = (u.y + w1.y + w2.y + w3.y) * inv;
        u.z = (u.z + w1.z + w2.z + w3.z) * inv;
        u.w = (u.w + w1.w + w2.w + w3.w) * inv;
        store_h4(&A2[(size_t)d * 512 + 256 + tt * 4], u);
    }
}

// ---------------------------------------------------------------------------
// Merged weight transpose+convert.
// ---------------------------------------------------------------------------
__global__ __launch_bounds__(256) void wcvt_all_kernel(const float* __restrict__ Wself1,
                                                       const float* __restrict__ Wneigh1,
                                                       const float* __restrict__ Ws2,
                                                       const float* __restrict__ Wn2,
                                                       __half* __restrict__ WT,
                                                       __half* __restrict__ WT2)
{
    const int idx = blockIdx.x * 256 + threadIdx.x;
    if (idx < 256 * 512) {
        const int n = idx >> 9;
        const int k = idx & 511;
        const float v = (k < 256) ? __ldg(&Wself1[(size_t)k * 256 + n])
                                  : __ldg(&Wneigh1[(size_t)(k - 256) * 256 + n]);
        WT[(size_t)n * 512 + k] = __float2half_rn(v);
    } else {
        const int j = idx - 256 * 512;
        const int n = j >> 9;
        const int k = j & 511;
        float v = 0.f;
        if (n < C_DIM)
            v = (k < 256) ? __ldg(&Ws2[(size_t)k * C_DIM + n])
                          : __ldg(&Wn2[(size_t)(k - 256) * C_DIM + n]);
        WT2[(size_t)n * 512 + k] = __float2half_rn(v);
    }
}

// ---------------------------------------------------------------------------
// ldmatrix / mma helpers
// ---------------------------------------------------------------------------
__device__ __forceinline__ void ldsm_x4(uint32_t& r0, uint32_t& r1, uint32_t& r2, uint32_t& r3,
                                        uint32_t addr) {
    asm volatile("ldmatrix.sync.aligned.m8n8.x4.shared.b16 {%0,%1,%2,%3}, [%4];\n"
                 : "=r"(r0), "=r"(r1), "=r"(r2), "=r"(r3) : "r"(addr));
}
__device__ __forceinline__ void mma_f16(float c[4], const uint32_t a[4], const uint32_t b[2]) {
    asm volatile(
        "mma.sync.aligned.m16n8k16.row.col.f32.f16.f16.f32 "
        "{%0,%1,%2,%3}, {%4,%5,%6,%7}, {%8,%9}, {%0,%1,%2,%3};\n"
        : "+f"(c[0]), "+f"(c[1]), "+f"(c[2]), "+f"(c[3])
        : "r"(a[0]), "r"(a[1]), "r"(a[2]), "r"(a[3]), "r"(b[0]), "r"(b[1]));
}

// ---------------------------------------------------------------------------
// Shared fp16 MMA mainloop (CTA 128x64, BK=32, 3-stage cp.async ring).
// ---------------------------------------------------------------------------
#define G1_BM 128
#define G1_BN 64
#define G1_BK 32
#define SRW 20
#define OFF_A 0
#define OFF_B (G1_BM * SRW)
#define STAGE_WORDS ((G1_BM + G1_BN) * SRW)
#define N_KTILES 16

struct MmaCtx {
    float acc[2][4][4];
    int wm, wn, g, tg;
};

__device__ __forceinline__ void run_mma_tile(
    const __half* __restrict__ Abase,
    const __half* __restrict__ Bbase,
    uint32_t* smem, MmaCtx& ctx)
{
    const int tid  = threadIdx.x;
    const int warp = tid >> 5;
    const int lane = tid & 31;
    ctx.wm = warp >> 1;
    ctx.wn = warp & 1;
    ctx.g  = lane >> 2;
    ctx.tg = lane & 3;

    uint32_t sbase;
    asm("{ .reg .u64 u; cvta.to.shared.u64 u, %1; cvt.u32.u64 %0, u; }"
        : "=r"(sbase) : "l"(smem));

    const int a_row0 = tid >> 2;
    const int a_ch   = tid & 3;

    const __half* gA0 = Abase + (size_t)a_row0 * 512 + a_ch * 8;
    const __half* gA1 = Abase + (size_t)(a_row0 + 64) * 512 + a_ch * 8;
    const __half* gB  = Bbase + (size_t)a_row0 * 512 + a_ch * 8;

    const uint32_t sA0 = sbase + (OFF_A + a_row0 * SRW + a_ch * 4) * 4;
    const uint32_t sA1 = sbase + (OFF_A + (a_row0 + 64) * SRW + a_ch * 4) * 4;
    const uint32_t sB  = sbase + (OFF_B + a_row0 * SRW + a_ch * 4) * 4;

    uint32_t aAddr[2];
#pragma unroll
    for (int i = 0; i < 2; ++i) {
        const int row = ctx.wm * 32 + i * 16 + (lane & 15);
        const int word = (lane >> 4) * 4;
        aAddr[i] = sbase + (OFF_A + row * SRW + word) * 4;
    }
    uint32_t bAddr[2];
#pragma unroll
    for (int p = 0; p < 2; ++p) {
        const int row = ctx.wn * 32 + p * 16 + (lane & 7) + ((lane >> 4) << 3);
        const int word = ((lane >> 3) & 1) * 4;
        bAddr[p] = sbase + (OFF_B + row * SRW + word) * 4;
    }
    const uint32_t stage_bytes = STAGE_WORDS * 4;

#pragma unroll
    for (int i = 0; i < 2; ++i)
#pragma unroll
        for (int j = 0; j < 4; ++j)
#pragma unroll
            for (int r = 0; r < 4; ++r) ctx.acc[i][j][r] = 0.f;

#pragma unroll
    for (int pt = 0; pt < 2; ++pt) {
        const uint32_t so = pt * stage_bytes;
        const int kn = pt * G1_BK;
        cp_async16(sA0 + so, gA0 + kn);
        cp_async16(sA1 + so, gA1 + kn);
        cp_async16(sB + so,  gB + kn);
        cp_commit();
    }

    int stage = 0;
    for (int t = 0; t < N_KTILES; ++t) {
        if (t + 1 < N_KTILES)
            asm volatile("cp.async.wait_group 1;" ::: "memory");
        else
            asm volatile("cp.async.wait_group 0;" ::: "memory");
        __syncthreads();

        if (t + 2 < N_KTILES) {
            const int kn = (t + 2) * G1_BK;
            const uint32_t so = ((stage + 2) % 3) * stage_bytes;
            cp_async16(sA0 + so, gA0 + kn);
            cp_async16(sA1 + so, gA1 + kn);
            cp_async16(sB + so,  gB + kn);
            cp_commit();
        }

        const uint32_t so = stage * stage_bytes;
#pragma unroll
        for (int s = 0; s < 2; ++s) {
            const uint32_t ko = so + s * 32;
            uint32_t Af[2][4], Bf[2][4];
#pragma unroll
            for (int i = 0; i < 2; ++i)
                ldsm_x4(Af[i][0], Af[i][1], Af[i][2], Af[i][3], aAddr[i] + ko);
#pragma unroll
            for (int p = 0; p < 2; ++p)
                ldsm_x4(Bf[p][0], Bf[p][1], Bf[p][2], Bf[p][3], bAddr[p] + ko);
#pragma unroll
            for (int i = 0; i < 2; ++i)
#pragma unroll
                for (int j = 0; j < 4; ++j) {
                    const uint32_t bf[2] = { Bf[j >> 1][(j & 1) * 2], Bf[j >> 1][(j & 1) * 2 + 1] };
                    mma_f16(ctx.acc[i][j], Af[i], bf);
                }
        }
        stage = (stage + 1) % 3;
    }
}

// ---------------------------------------------------------------------------
// Layer-1 GEMM: h = relu(A @ WT^T + b1)
// ---------------------------------------------------------------------------
__global__ __launch_bounds__(256) void gemm1_kernel(
    const __half* __restrict__ A,
    const __half* __restrict__ WT,
    const float* __restrict__ bias,
    float* __restrict__ out)
{
    __shared__ __align__(16) uint32_t smem[3 * STAGE_WORDS];
    const int bx = blockIdx.x;
    const int by = blockIdx.y;

    MmaCtx ctx;
    run_mma_tile(A + (size_t)(by * G1_BM) * 512, WT + (size_t)(bx * G1_BN) * 512, smem, ctx);

#pragma unroll
    for (int i = 0; i < 2; ++i) {
#pragma unroll
        for (int j = 0; j < 4; ++j) {
            const int col = bx * G1_BN + ctx.wn * 32 + j * 8 + ctx.tg * 2;
            const float b0 = __ldg(&bias[col]);
            const float b1 = __ldg(&bias[col + 1]);
            const int r0 = by * G1_BM + ctx.wm * 32 + i * 16 + ctx.g;
            float2 v0;
            v0.x = fmaxf(ctx.acc[i][j][0] + b0, 0.f);
            v0.y = fmaxf(ctx.acc[i][j][1] + b1, 0.f);
            *reinterpret_cast<float2*>(&out[(size_t)r0 * 256 + col]) = v0;
            float2 v1;
            v1.x = fmaxf(ctx.acc[i][j][2] + b0, 0.f);
            v1.y = fmaxf(ctx.acc[i][j][3] + b1, 0.f);
            *reinterpret_cast<float2*>(&out[(size_t)(r0 + 8) * 256 + col]) = v1;
        }
    }
}

// ---------------------------------------------------------------------------
// Layer-2 GEMM: out = A2 @ WT2^T + b2 (no relu), cols >= 47 dropped.
// ---------------------------------------------------------------------------
__global__ __launch_bounds__(256) void gemm2_tc_kernel(
    const __half* __restrict__ A2,
    const __half* __restrict__ WT2,
    const float* __restrict__ bias,
    float* __restrict__ out)
{
    __shared__ __align__(16) uint32_t smem[3 * STAGE_WORDS];
    const int by = blockIdx.x;

    MmaCtx ctx;
    run_mma_tile(A2 + (size_t)(by * G1_BM) * 512, WT2, smem, ctx);

#pragma unroll
    for (int i = 0; i < 2; ++i) {
#pragma unroll
        for (int j = 0; j < 4; ++j) {
            const int col = ctx.wn * 32 + j * 8 + ctx.tg * 2;
            const int r0 = by * G1_BM + ctx.wm * 32 + i * 16 + ctx.g;
            if (col < C_DIM) {
                const float b0 = __ldg(&bias[col]);
                out[(size_t)r0 * C_DIM + col]       = ctx.acc[i][j][0] + b0;
                out[(size_t)(r0 + 8) * C_DIM + col] = ctx.acc[i][j][2] + b0;
            }
            if (col + 1 < C_DIM) {
                const float b1 = __ldg(&bias[col + 1]);
                out[(size_t)r0 * C_DIM + col + 1]       = ctx.acc[i][j][1] + b1;
                out[(size_t)(r0 + 8) * C_DIM + col + 1] = ctx.acc[i][j][3] + b1;
            }
        }
    }
}

// ---------------------------------------------------------------------------
// Launch
// ---------------------------------------------------------------------------
extern "C" void kernel_launch(void* const* d_in, const int* in_sizes, int n_in,
                              void* d_out, int out_size)
{
    const float* x       = (const float*)d_in[0];
    const int*   src1    = (const int*)  d_in[1];
    const int*   dst1    = (const int*)  d_in[2];
    const int*   src2    = (const int*)  d_in[3];
    const int*   dst2    = (const int*)  d_in[4];
    const float* Wself1  = (const float*)d_in[5];
    const float* Wneigh1 = (const float*)d_in[6];
    const float* b1      = (const float*)d_in[7];
    const float* Wself2  = (const float*)d_in[8];
    const float* Wneigh2 = (const float*)d_in[9];
    const float* b2      = (const float*)d_in[10];
    float* out = (float*)d_out;

    __half *A, *WT, *A2, *WT2;
    float* hbuf;
    cudaGetSymbolAddress((void**)&A,   g_A);
    cudaGetSymbolAddress((void**)&WT,  g_WT);
    cudaGetSymbolAddress((void**)&A2,  g_A2);
    cudaGetSymbolAddress((void**)&WT2, g_WT2);
    cudaGetSymbolAddress((void**)&hbuf, g_h);

    // Prep: merged weight transpose+convert (both layers)
    wcvt_all_kernel<<<(320 * 512) / 256, 256>>>(Wself1, Wneigh1, Wself2, Wneigh2, WT, WT2);

    // Layer 1: cp.async-pipelined aggregation + fused x convert
    agg1_kernel<<<N_DST1, 128>>>(x, src1, dst1, A);

    // Layer 1 GEMM + bias + relu
    dim3 g1(H_DIM / G1_BN, N_DST1 / G1_BM);   // (4, 88)
    gemm1_kernel<<<g1, 256>>>(A, WT, b1, hbuf);

    // Layer 2: aggregate + GEMM
    agg2_kernel<<<N_DST2, 256>>>(hbuf, src2, dst2, A2);
    gemm2_tc_kernel<<<N_DST2 / G1_BM, 256>>>(A2, WT2, b2, out);
}

// round 17
// speedup vs baseline: 1.0546x; 1.0546x over previous
#include <cuda_runtime.h>
#include <cuda_fp16.h>
#include <cstdint>

// Problem constants
#define N_SRC1  292864
#define N_DST1  11264
#define N_E1    281600
#define N_DST2  1024
#define N_E2    10240
#define IN_DIM  256
#define H_DIM   256
#define C_DIM   47

// Scratch (device globals — no allocation allowed)
__device__ __half g_A[N_DST1 * 512];      // [x_dst | hneigh1] fp16
__device__ __half g_WT[256 * 512];        // [Wself1;Wneigh1]^T fp16
__device__ float  g_h[N_DST1 * H_DIM];    // relu(layer-1 out) fp32
__device__ __half g_A2[N_DST2 * 512];     // [h_dst | hneigh2] fp16
__device__ __half g_WT2[64 * 512];        // [Wself2;Wneigh2]^T fp16, cols 47-63 zero

// ---------------------------------------------------------------------------
// fp16 helpers
// ---------------------------------------------------------------------------
__device__ __forceinline__ uint32_t pack_h2(float f0, float f1) {
    const __half h0 = __float2half_rn(f0);
    const __half h1 = __float2half_rn(f1);
    return (uint32_t)__half_as_ushort(h0) | ((uint32_t)__half_as_ushort(h1) << 16);
}
__device__ __forceinline__ void store_h4(__half* p, float4 v) {
    uint2 u;
    u.x = pack_h2(v.x, v.y);
    u.y = pack_h2(v.z, v.w);
    *reinterpret_cast<uint2*>(p) = u;
}

// ---------------------------------------------------------------------------
// Layer-1 mean aggregation + fused x convert + fused weight convert.
// 128 thr/dst, 2 edge streams, 2x unroll, regs capped for full occupancy.
// Blocks 0..639 additionally convert 256 weight elements each (both layers).
// ---------------------------------------------------------------------------
__global__ __launch_bounds__(128, 16) void agg1_kernel(const float* __restrict__ feat,
                                                       const int* __restrict__ src_idx,
                                                       const int* __restrict__ dst_idx,
                                                       const float* __restrict__ Wself1,
                                                       const float* __restrict__ Wneigh1,
                                                       const float* __restrict__ Ws2,
                                                       const float* __restrict__ Wn2,
                                                       __half* __restrict__ A,
                                                       __half* __restrict__ WT,
                                                       __half* __restrict__ WT2)
{
    const int d = blockIdx.x;
    const int t = threadIdx.x;

    // ---- fused weight conversion (blocks 0..639, 2 elements per thread) ----
    if (d < 640) {
#pragma unroll
        for (int q = 0; q < 2; ++q) {
            const int idx = d * 256 + q * 128 + t;   // [0, 163840)
            if (idx < 256 * 512) {
                const int n = idx >> 9;
                const int k = idx & 511;
                const float v = (k < 256) ? __ldg(&Wself1[(size_t)k * 256 + n])
                                          : __ldg(&Wneigh1[(size_t)(k - 256) * 256 + n]);
                WT[(size_t)n * 512 + k] = __float2half_rn(v);
            } else {
                const int j = idx - 256 * 512;
                const int n = j >> 9;
                const int k = j & 511;
                float v = 0.f;
                if (n < C_DIM)
                    v = (k < 256) ? __ldg(&Ws2[(size_t)k * C_DIM + n])
                                  : __ldg(&Wn2[(size_t)(k - 256) * C_DIM + n]);
                WT2[(size_t)n * 512 + k] = __float2half_rn(v);
            }
        }
    }

    int lo = 0, hi = N_E1;
    while (lo < hi) { int mid = (lo + hi) >> 1; if (__ldg(&dst_idx[mid]) < d) lo = mid + 1; else hi = mid; }
    const int start = lo;
    hi = N_E1;
    while (lo < hi) { int mid = (lo + hi) >> 1; if (__ldg(&dst_idx[mid]) <= d) lo = mid + 1; else hi = mid; }
    const int end = lo;

    const int half = t >> 6;            // 0/1 edge stream
    const int tt   = t & 63;            // float4 slice of the 256-dim row

    __shared__ float a_nb[2][256];

    float4 acc0 = make_float4(0.f, 0.f, 0.f, 0.f);
    float4 acc1 = make_float4(0.f, 0.f, 0.f, 0.f);

    int e = start + half;
    for (; e + 2 < end; e += 4) {
        const int s0 = __ldg(&src_idx[e]);
        const int s1 = __ldg(&src_idx[e + 2]);
        const float4 v0 = *reinterpret_cast<const float4*>(&feat[(size_t)s0 * 256 + tt * 4]);
        const float4 v1 = *reinterpret_cast<const float4*>(&feat[(size_t)s1 * 256 + tt * 4]);
        acc0.x += v0.x; acc0.y += v0.y; acc0.z += v0.z; acc0.w += v0.w;
        acc1.x += v1.x; acc1.y += v1.y; acc1.z += v1.z; acc1.w += v1.w;
    }
    for (; e < end; e += 2) {
        const int s = __ldg(&src_idx[e]);
        const float4 v = *reinterpret_cast<const float4*>(&feat[(size_t)s * 256 + tt * 4]);
        acc0.x += v.x; acc0.y += v.y; acc0.z += v.z; acc0.w += v.w;
    }
    acc0.x += acc1.x; acc0.y += acc1.y; acc0.z += acc1.z; acc0.w += acc1.w;
    *reinterpret_cast<float4*>(&a_nb[half][tt * 4]) = acc0;

    // fused xcvt: stream-1 threads convert the self row while stream-0 reduces
    if (half == 1) {
        const float4 v = *reinterpret_cast<const float4*>(&feat[(size_t)d * 256 + tt * 4]);
        store_h4(&A[(size_t)d * 512 + tt * 4], v);
    }
    __syncthreads();

    if (half == 0) {
        const int deg = end - start;
        const float inv = (deg > 0) ? 1.0f / (float)deg : 0.0f;
        float4 u = *reinterpret_cast<float4*>(&a_nb[0][tt * 4]);
        const float4 w = *reinterpret_cast<float4*>(&a_nb[1][tt * 4]);
        u.x = (u.x + w.x) * inv; u.y = (u.y + w.y) * inv;
        u.z = (u.z + w.z) * inv; u.w = (u.w + w.w) * inv;
        store_h4(&A[(size_t)d * 512 + 256 + tt * 4], u);
    }
}

// ---------------------------------------------------------------------------
// Layer-2 aggregation + self copy: 1024 blocks x 256 thr, 4 edge streams.
// ---------------------------------------------------------------------------
__global__ __launch_bounds__(256, 8) void agg2_kernel(const float* __restrict__ h,
                                                      const int* __restrict__ src_idx,
                                                      const int* __restrict__ dst_idx,
                                                      __half* __restrict__ A2)
{
    const int d = blockIdx.x;

    int lo = 0, hi = N_E2;
    while (lo < hi) { int mid = (lo + hi) >> 1; if (__ldg(&dst_idx[mid]) < d) lo = mid + 1; else hi = mid; }
    const int start = lo;
    hi = N_E2;
    while (lo < hi) { int mid = (lo + hi) >> 1; if (__ldg(&dst_idx[mid]) <= d) lo = mid + 1; else hi = mid; }
    const int end = lo;

    const int t  = threadIdx.x;
    const int qs = t >> 6;              // 0..3 edge stream
    const int tt = t & 63;              // float4 slice

    __shared__ float a_nb[4][256];

    float4 acc0 = make_float4(0.f, 0.f, 0.f, 0.f);
    float4 acc1 = make_float4(0.f, 0.f, 0.f, 0.f);

    int e = start + qs;
    for (; e + 4 < end; e += 8) {
        const int s0 = __ldg(&src_idx[e]);
        const int s1 = __ldg(&src_idx[e + 4]);
        const float4 v0 = *reinterpret_cast<const float4*>(&h[(size_t)s0 * 256 + tt * 4]);
        const float4 v1 = *reinterpret_cast<const float4*>(&h[(size_t)s1 * 256 + tt * 4]);
        acc0.x += v0.x; acc0.y += v0.y; acc0.z += v0.z; acc0.w += v0.w;
        acc1.x += v1.x; acc1.y += v1.y; acc1.z += v1.z; acc1.w += v1.w;
    }
    for (; e < end; e += 4) {
        const int s = __ldg(&src_idx[e]);
        const float4 v = *reinterpret_cast<const float4*>(&h[(size_t)s * 256 + tt * 4]);
        acc0.x += v.x; acc0.y += v.y; acc0.z += v.z; acc0.w += v.w;
    }
    acc0.x += acc1.x; acc0.y += acc1.y; acc0.z += acc1.z; acc0.w += acc1.w;
    *reinterpret_cast<float4*>(&a_nb[qs][tt * 4]) = acc0;

    if (qs == 1) {
        const float4 v = *reinterpret_cast<const float4*>(&h[(size_t)d * 256 + tt * 4]);
        store_h4(&A2[(size_t)d * 512 + tt * 4], v);
    }
    __syncthreads();

    if (qs == 0) {
        const int deg = end - start;
        const float inv = (deg > 0) ? 1.0f / (float)deg : 0.0f;
        float4 u = *reinterpret_cast<float4*>(&a_nb[0][tt * 4]);
        const float4 w1 = *reinterpret_cast<float4*>(&a_nb[1][tt * 4]);
        const float4 w2 = *reinterpret_cast<float4*>(&a_nb[2][tt * 4]);
        const float4 w3 = *reinterpret_cast<float4*>(&a_nb[3][tt * 4]);
        u.x = (u.x + w1.x + w2.x + w3.x) * inv;
        u.y = (u.y + w1.y + w2.y + w3.y) * inv;
        u.z = (u.z + w1.z + w2.z + w3.z) * inv;
        u.w = (u.w + w1.w + w2.w + w3.w) * inv;
        store_h4(&A2[(size_t)d * 512 + 256 + tt * 4], u);
    }
}

// ---------------------------------------------------------------------------
// cp.async / ldmatrix helpers
// ---------------------------------------------------------------------------
__device__ __forceinline__ void cp_async16(uint32_t saddr, const void* g) {
    asm volatile("cp.async.ca.shared.global [%0], [%1], 16;\n" :: "r"(saddr), "l"(g));
}
__device__ __forceinline__ void cp_commit() {
    asm volatile("cp.async.commit_group;\n" ::: "memory");
}
__device__ __forceinline__ void ldsm_x4(uint32_t& r0, uint32_t& r1, uint32_t& r2, uint32_t& r3,
                                        uint32_t addr) {
    asm volatile("ldmatrix.sync.aligned.m8n8.x4.shared.b16 {%0,%1,%2,%3}, [%4];\n"
                 : "=r"(r0), "=r"(r1), "=r"(r2), "=r"(r3) : "r"(addr));
}
__device__ __forceinline__ void mma_f16(float c[4], const uint32_t a[4], const uint32_t b[2]) {
    asm volatile(
        "mma.sync.aligned.m16n8k16.row.col.f32.f16.f16.f32 "
        "{%0,%1,%2,%3}, {%4,%5,%6,%7}, {%8,%9}, {%0,%1,%2,%3};\n"
        : "+f"(c[0]), "+f"(c[1]), "+f"(c[2]), "+f"(c[3])
        : "r"(a[0]), "r"(a[1]), "r"(a[2]), "r"(a[3]), "r"(b[0]), "r"(b[1]));
}

// ---------------------------------------------------------------------------
// Shared fp16 MMA mainloop (CTA 128x64, BK=32, 3-stage cp.async ring).
// ---------------------------------------------------------------------------
#define G1_BM 128
#define G1_BN 64
#define G1_BK 32
#define SRW 20
#define OFF_A 0
#define OFF_B (G1_BM * SRW)
#define STAGE_WORDS ((G1_BM + G1_BN) * SRW)
#define N_KTILES 16

struct MmaCtx {
    float acc[2][4][4];
    int wm, wn, g, tg;
};

__device__ __forceinline__ void run_mma_tile(
    const __half* __restrict__ Abase,
    const __half* __restrict__ Bbase,
    uint32_t* smem, MmaCtx& ctx)
{
    const int tid  = threadIdx.x;
    const int warp = tid >> 5;
    const int lane = tid & 31;
    ctx.wm = warp >> 1;
    ctx.wn = warp & 1;
    ctx.g  = lane >> 2;
    ctx.tg = lane & 3;

    uint32_t sbase;
    asm("{ .reg .u64 u; cvta.to.shared.u64 u, %1; cvt.u32.u64 %0, u; }"
        : "=r"(sbase) : "l"(smem));

    const int a_row0 = tid >> 2;
    const int a_ch   = tid & 3;

    const __half* gA0 = Abase + (size_t)a_row0 * 512 + a_ch * 8;
    const __half* gA1 = Abase + (size_t)(a_row0 + 64) * 512 + a_ch * 8;
    const __half* gB  = Bbase + (size_t)a_row0 * 512 + a_ch * 8;

    const uint32_t sA0 = sbase + (OFF_A + a_row0 * SRW + a_ch * 4) * 4;
    const uint32_t sA1 = sbase + (OFF_A + (a_row0 + 64) * SRW + a_ch * 4) * 4;
    const uint32_t sB  = sbase + (OFF_B + a_row0 * SRW + a_ch * 4) * 4;

    uint32_t aAddr[2];
#pragma unroll
    for (int i = 0; i < 2; ++i) {
        const int row = ctx.wm * 32 + i * 16 + (lane & 15);
        const int word = (lane >> 4) * 4;
        aAddr[i] = sbase + (OFF_A + row * SRW + word) * 4;
    }
    uint32_t bAddr[2];
#pragma unroll
    for (int p = 0; p < 2; ++p) {
        const int row = ctx.wn * 32 + p * 16 + (lane & 7) + ((lane >> 4) << 3);
        const int word = ((lane >> 3) & 1) * 4;
        bAddr[p] = sbase + (OFF_B + row * SRW + word) * 4;
    }
    const uint32_t stage_bytes = STAGE_WORDS * 4;

#pragma unroll
    for (int i = 0; i < 2; ++i)
#pragma unroll
        for (int j = 0; j < 4; ++j)
#pragma unroll
            for (int r = 0; r < 4; ++r) ctx.acc[i][j][r] = 0.f;

#pragma unroll
    for (int pt = 0; pt < 2; ++pt) {
        const uint32_t so = pt * stage_bytes;
        const int kn = pt * G1_BK;
        cp_async16(sA0 + so, gA0 + kn);
        cp_async16(sA1 + so, gA1 + kn);
        cp_async16(sB + so,  gB + kn);
        cp_commit();
    }

    int stage = 0;
    for (int t = 0; t < N_KTILES; ++t) {
        if (t + 1 < N_KTILES)
            asm volatile("cp.async.wait_group 1;" ::: "memory");
        else
            asm volatile("cp.async.wait_group 0;" ::: "memory");
        __syncthreads();

        if (t + 2 < N_KTILES) {
            const int kn = (t + 2) * G1_BK;
            const uint32_t so = ((stage + 2) % 3) * stage_bytes;
            cp_async16(sA0 + so, gA0 + kn);
            cp_async16(sA1 + so, gA1 + kn);
            cp_async16(sB + so,  gB + kn);
            cp_commit();
        }

        const uint32_t so = stage * stage_bytes;
#pragma unroll
        for (int s = 0; s < 2; ++s) {
            const uint32_t ko = so + s * 32;
            uint32_t Af[2][4], Bf[2][4];
#pragma unroll
            for (int i = 0; i < 2; ++i)
                ldsm_x4(Af[i][0], Af[i][1], Af[i][2], Af[i][3], aAddr[i] + ko);
#pragma unroll
            for (int p = 0; p < 2; ++p)
                ldsm_x4(Bf[p][0], Bf[p][1], Bf[p][2], Bf[p][3], bAddr[p] + ko);
#pragma unroll
            for (int i = 0; i < 2; ++i)
#pragma unroll
                for (int j = 0; j < 4; ++j) {
                    const uint32_t bf[2] = { Bf[j >> 1][(j & 1) * 2], Bf[j >> 1][(j & 1) * 2 + 1] };
                    mma_f16(ctx.acc[i][j], Af[i], bf);
                }
        }
        stage = (stage + 1) % 3;
    }
}

// ---------------------------------------------------------------------------
// Layer-1 GEMM: h = relu(A @ WT^T + b1)
// ---------------------------------------------------------------------------
__global__ __launch_bounds__(256) void gemm1_kernel(
    const __half* __restrict__ A,
    const __half* __restrict__ WT,
    const float* __restrict__ bias,
    float* __restrict__ out)
{
    __shared__ __align__(16) uint32_t smem[3 * STAGE_WORDS];
    const int bx = blockIdx.x;
    const int by = blockIdx.y;

    MmaCtx ctx;
    run_mma_tile(A + (size_t)(by * G1_BM) * 512, WT + (size_t)(bx * G1_BN) * 512, smem, ctx);

#pragma unroll
    for (int i = 0; i < 2; ++i) {
#pragma unroll
        for (int j = 0; j < 4; ++j) {
            const int col = bx * G1_BN + ctx.wn * 32 + j * 8 + ctx.tg * 2;
            const float b0 = __ldg(&bias[col]);
            const float b1 = __ldg(&bias[col + 1]);
            const int r0 = by * G1_BM + ctx.wm * 32 + i * 16 + ctx.g;
            float2 v0;
            v0.x = fmaxf(ctx.acc[i][j][0] + b0, 0.f);
            v0.y = fmaxf(ctx.acc[i][j][1] + b1, 0.f);
            *reinterpret_cast<float2*>(&out[(size_t)r0 * 256 + col]) = v0;
            float2 v1;
            v1.x = fmaxf(ctx.acc[i][j][2] + b0, 0.f);
            v1.y = fmaxf(ctx.acc[i][j][3] + b1, 0.f);
            *reinterpret_cast<float2*>(&out[(size_t)(r0 + 8) * 256 + col]) = v1;
        }
    }
}

// ---------------------------------------------------------------------------
// Layer-2 GEMM: out = A2 @ WT2^T + b2 (no relu), cols >= 47 dropped.
// ---------------------------------------------------------------------------
__global__ __launch_bounds__(256) void gemm2_tc_kernel(
    const __half* __restrict__ A2,
    const __half* __restrict__ WT2,
    const float* __restrict__ bias,
    float* __restrict__ out)
{
    __shared__ __align__(16) uint32_t smem[3 * STAGE_WORDS];
    const int by = blockIdx.x;

    MmaCtx ctx;
    run_mma_tile(A2 + (size_t)(by * G1_BM) * 512, WT2, smem, ctx);

#pragma unroll
    for (int i = 0; i < 2; ++i) {
#pragma unroll
        for (int j = 0; j < 4; ++j) {
            const int col = ctx.wn * 32 + j * 8 + ctx.tg * 2;
            const int r0 = by * G1_BM + ctx.wm * 32 + i * 16 + ctx.g;
            if (col < C_DIM) {
                const float b0 = __ldg(&bias[col]);
                out[(size_t)r0 * C_DIM + col]       = ctx.acc[i][j][0] + b0;
                out[(size_t)(r0 + 8) * C_DIM + col] = ctx.acc[i][j][2] + b0;
            }
            if (col + 1 < C_DIM) {
                const float b1 = __ldg(&bias[col + 1]);
                out[(size_t)r0 * C_DIM + col + 1]       = ctx.acc[i][j][1] + b1;
                out[(size_t)(r0 + 8) * C_DIM + col + 1] = ctx.acc[i][j][3] + b1;
            }
        }
    }
}

// ---------------------------------------------------------------------------
// Launch
// ---------------------------------------------------------------------------
extern "C" void kernel_launch(void* const* d_in, const int* in_sizes, int n_in,
                              void* d_out, int out_size)
{
    const float* x       = (const float*)d_in[0];
    const int*   src1    = (const int*)  d_in[1];
    const int*   dst1    = (const int*)  d_in[2];
    const int*   src2    = (const int*)  d_in[3];
    const int*   dst2    = (const int*)  d_in[4];
    const float* Wself1  = (const float*)d_in[5];
    const float* Wneigh1 = (const float*)d_in[6];
    const float* b1      = (const float*)d_in[7];
    const float* Wself2  = (const float*)d_in[8];
    const float* Wneigh2 = (const float*)d_in[9];
    const float* b2      = (const float*)d_in[10];
    float* out = (float*)d_out;

    __half *A, *WT, *A2, *WT2;
    float* hbuf;
    cudaGetSymbolAddress((void**)&A,   g_A);
    cudaGetSymbolAddress((void**)&WT,  g_WT);
    cudaGetSymbolAddress((void**)&A2,  g_A2);
    cudaGetSymbolAddress((void**)&WT2, g_WT2);
    cudaGetSymbolAddress((void**)&hbuf, g_h);

    // Layer 1: aggregation + fused x convert + fused weight convert
    agg1_kernel<<<N_DST1, 128>>>(x, src1, dst1, Wself1, Wneigh1, Wself2, Wneigh2,
                                 A, WT, WT2);

    // Layer 1 GEMM + bias + relu
    dim3 g1(H_DIM / G1_BN, N_DST1 / G1_BM);   // (4, 88)
    gemm1_kernel<<<g1, 256>>>(A, WT, b1, hbuf);

    // Layer 2: aggregate + GEMM
    agg2_kernel<<<N_DST2, 256>>>(hbuf, src2, dst2, A2);
    gemm2_tc_kernel<<<N_DST2 / G1_BM, 256>>>(A2, WT2, b2, out);
}